// round 13
// baseline (speedup 1.0000x reference)
#include <cuda_runtime.h>
#include <cuda_fp16.h>
#include <math.h>
#include <float.h>

#define MAX_NODES 100000
#define MAX_EDGES 1600000
#define SCAN_TILE 1024
#define MAX_SCAN_BLOCKS 128

// Scratch — referenced directly from device code.
// g_bufA viewed as __half[...] (gather operand); g_bufB stays fp32.
__device__ __align__(16) float g_bufA[MAX_NODES * 64];
__device__ __align__(16) float g_bufB[MAX_NODES * 64];
__device__ __align__(16) int g_deg_out[MAX_NODES];
__device__ __align__(16) int g_deg_in[MAX_NODES];
__device__ int   g_rowptr[MAX_NODES + 1];
__device__ int   g_cursor[MAX_NODES];
__device__ int   g_col[MAX_EDGES];
__device__ __align__(16) float g_ns[MAX_NODES];
__device__ __align__(16) float g_nd[MAX_NODES];
__device__ int   g_blksum[MAX_SCAN_BLOCKS];
__device__ int   g_blkoff[MAX_SCAN_BLOCKS];

// Register-only fp16x2 -> float2 conversion (no address-of -> no local spill).
__device__ __forceinline__ float2 h2f2(unsigned v) {
    float2 f;
    asm("{\n\t.reg .b16 lo, hi;\n\t"
        "mov.b32 {lo, hi}, %2;\n\t"
        "cvt.f32.f16 %0, lo;\n\t"
        "cvt.f32.f16 %1, hi;\n\t}"
        : "=f"(f.x), "=f"(f.y) : "r"(v));
    return f;
}

// ---------------------------------------------------------------------------
__global__ void zero_deg_kernel(int n) {
    int i = blockIdx.x * blockDim.x + threadIdx.x;
    if (i < n) { g_deg_out[i] = 0; g_deg_in[i] = 0; }
}

__global__ void deg_kernel(const int* __restrict__ src,
                           const int* __restrict__ dst, int E) {
    int i = blockIdx.x * blockDim.x + threadIdx.x;
    if (i < E) {
        atomicAdd(&g_deg_out[src[i]], 1);
        atomicAdd(&g_deg_in[dst[i]], 1);
    }
}

// ---------------------------------------------------------------------------
// Grid-wide exclusive scan of g_deg_in -> g_rowptr/g_cursor (+ fused norms).
// ---------------------------------------------------------------------------
__device__ __forceinline__ int warp_incl_scan(int v, int lane) {
#pragma unroll
    for (int o = 1; o < 32; o <<= 1) {
        int t = __shfl_up_sync(0xffffffffu, v, o);
        if (lane >= o) v += t;
    }
    return v;
}

__global__ void scan_reduce_kernel(int n) {
    __shared__ int wsum[8];
    int tid = threadIdx.x, lane = tid & 31, wid = tid >> 5;
    int base = blockIdx.x * SCAN_TILE + tid * 4;
    int s = 0;
    if (base < n) {
        int4 v = *reinterpret_cast<const int4*>(&g_deg_in[base]);
        s = v.x + v.y + v.z + v.w;
    }
#pragma unroll
    for (int o = 16; o > 0; o >>= 1) s += __shfl_xor_sync(0xffffffffu, s, o);
    if (lane == 0) wsum[wid] = s;
    __syncthreads();
    if (tid == 0) {
        int t = 0;
#pragma unroll
        for (int w = 0; w < 8; w++) t += wsum[w];
        g_blksum[blockIdx.x] = t;
    }
}

__global__ void scan_blksums_kernel(int nb, int n) {
    __shared__ int woff[4];
    int tid = threadIdx.x, lane = tid & 31, wid = tid >> 5;
    int v = (tid < nb) ? g_blksum[tid] : 0;
    int incl = warp_incl_scan(v, lane);
    if (lane == 31) woff[wid] = incl;
    __syncthreads();
    if (tid == 0) {
        int acc = 0;
#pragma unroll
        for (int w = 0; w < 4; w++) { int t = woff[w]; woff[w] = acc; acc += t; }
    }
    __syncthreads();
    int excl = incl - v + woff[wid];
    if (tid < nb) g_blkoff[tid] = excl;
    if (tid == nb - 1) g_rowptr[n] = excl + v;
}

__device__ __forceinline__ float deg_norm(int d) {
    return (d > 0) ? rsqrtf((float)d) : 0.0f;
}

__global__ void scan_write_kernel(int n) {
    __shared__ int woff[8];
    int tid = threadIdx.x, lane = tid & 31, wid = tid >> 5;
    int base = blockIdx.x * SCAN_TILE + tid * 4;
    int4 v = make_int4(0, 0, 0, 0);
    if (base < n) v = *reinterpret_cast<const int4*>(&g_deg_in[base]);
    int s = v.x + v.y + v.z + v.w;
    int incl = warp_incl_scan(s, lane);
    if (lane == 31) woff[wid] = incl;
    __syncthreads();
    if (tid == 0) {
        int acc = 0;
#pragma unroll
        for (int w = 0; w < 8; w++) { int t = woff[w]; woff[w] = acc; acc += t; }
    }
    __syncthreads();
    if (base < n) {
        int excl = incl - s + woff[wid] + g_blkoff[blockIdx.x];
        int p0 = excl, p1 = p0 + v.x, p2 = p1 + v.y, p3 = p2 + v.z;
        *reinterpret_cast<int4*>(&g_rowptr[base]) = make_int4(p0, p1, p2, p3);
        *reinterpret_cast<int4*>(&g_cursor[base]) = make_int4(p0, p1, p2, p3);
        int4 o = *reinterpret_cast<const int4*>(&g_deg_out[base]);
        *reinterpret_cast<float4*>(&g_ns[base]) =
            make_float4(deg_norm(o.x), deg_norm(o.y), deg_norm(o.z), deg_norm(o.w));
        *reinterpret_cast<float4*>(&g_nd[base]) =
            make_float4(deg_norm(v.x), deg_norm(v.y), deg_norm(v.z), deg_norm(v.w));
    }
}

__global__ void fill_kernel(const int* __restrict__ src,
                            const int* __restrict__ dst, int E) {
    int e = blockIdx.x * blockDim.x + threadIdx.x;
    if (e < E) {
        int d = dst[e];
        int pos = atomicAdd(&g_cursor[d], 1);
        g_col[pos] = src[e];
    }
}

// ---------------------------------------------------------------------------
// GEMM (packed f32x2): halfA[M,N] = half((X[M,K] @ W[K,N]) [* g_ns[row]])
// ---------------------------------------------------------------------------
#define AS_S 68

template<int K, int N, bool SCALE_NS>
__global__ void gemm_ns_kernel(const float* __restrict__ Xext,
                               const float* __restrict__ W, int M) {
    __shared__ __align__(16) float Ws[K * 64];
    __shared__ __align__(16) float As[32 * AS_S];

    const float* X = Xext ? Xext : g_bufB;
    __half* outh = reinterpret_cast<__half*>(g_bufA);
    const int tid = threadIdx.x;
    const int tr = tid >> 4;
    const int tc = tid & 15;
    const int row0 = blockIdx.x * 64;

    for (int t = tid; t < K * 64; t += 256) {
        int k = t >> 6, c = t & 63;
        Ws[t] = (c < N) ? W[k * N + c] : 0.0f;
    }

    unsigned long long acc[2][4];
#pragma unroll
    for (int rp = 0; rp < 2; rp++)
#pragma unroll
        for (int c = 0; c < 4; c++) acc[rp][c] = 0ull;

    for (int k0 = 0; k0 < K; k0 += 32) {
        __syncthreads();
#pragma unroll
        for (int it = 0; it < 2; it++) {
            int idx = tid + it * 256;
            int row = idx >> 3;
            int kc = idx & 7;
            float4 v = make_float4(0.f, 0.f, 0.f, 0.f);
            if (row0 + row < M)
                v = *reinterpret_cast<const float4*>(&X[(long long)(row0 + row) * K + k0 + kc * 4]);
            As[(kc * 4 + 0) * AS_S + row] = v.x;
            As[(kc * 4 + 1) * AS_S + row] = v.y;
            As[(kc * 4 + 2) * AS_S + row] = v.z;
            As[(kc * 4 + 3) * AS_S + row] = v.w;
        }
        __syncthreads();

#pragma unroll
        for (int kk = 0; kk < 32; kk++) {
            float4 a4 = *reinterpret_cast<const float4*>(&As[kk * AS_S + tr * 4]);
            float4 b4 = *reinterpret_cast<const float4*>(&Ws[(k0 + kk) * 64 + tc * 4]);
            unsigned long long a01, a23, bb0, bb1, bb2, bb3;
            asm("mov.b64 %0, {%1, %2};" : "=l"(a01) : "f"(a4.x), "f"(a4.y));
            asm("mov.b64 %0, {%1, %2};" : "=l"(a23) : "f"(a4.z), "f"(a4.w));
            asm("mov.b64 %0, {%1, %1};" : "=l"(bb0) : "f"(b4.x));
            asm("mov.b64 %0, {%1, %1};" : "=l"(bb1) : "f"(b4.y));
            asm("mov.b64 %0, {%1, %1};" : "=l"(bb2) : "f"(b4.z));
            asm("mov.b64 %0, {%1, %1};" : "=l"(bb3) : "f"(b4.w));
            asm("fma.rn.f32x2 %0, %1, %2, %0;" : "+l"(acc[0][0]) : "l"(a01), "l"(bb0));
            asm("fma.rn.f32x2 %0, %1, %2, %0;" : "+l"(acc[0][1]) : "l"(a01), "l"(bb1));
            asm("fma.rn.f32x2 %0, %1, %2, %0;" : "+l"(acc[0][2]) : "l"(a01), "l"(bb2));
            asm("fma.rn.f32x2 %0, %1, %2, %0;" : "+l"(acc[0][3]) : "l"(a01), "l"(bb3));
            asm("fma.rn.f32x2 %0, %1, %2, %0;" : "+l"(acc[1][0]) : "l"(a23), "l"(bb0));
            asm("fma.rn.f32x2 %0, %1, %2, %0;" : "+l"(acc[1][1]) : "l"(a23), "l"(bb1));
            asm("fma.rn.f32x2 %0, %1, %2, %0;" : "+l"(acc[1][2]) : "l"(a23), "l"(bb2));
            asm("fma.rn.f32x2 %0, %1, %2, %0;" : "+l"(acc[1][3]) : "l"(a23), "l"(bb3));
        }
    }

#pragma unroll
    for (int rp = 0; rp < 2; rp++) {
        float lo[4], hi[4];
#pragma unroll
        for (int c = 0; c < 4; c++)
            asm("mov.b64 {%0, %1}, %2;" : "=f"(lo[c]), "=f"(hi[c]) : "l"(acc[rp][c]));
        int rlo = row0 + tr * 4 + rp * 2;
        int rhi = rlo + 1;
        if (rlo < M && tc * 4 < N) {
            float s = SCALE_NS ? g_ns[rlo] : 1.0f;
            __half2* p = reinterpret_cast<__half2*>(&outh[(long long)rlo * N + tc * 4]);
            p[0] = __floats2half2_rn(lo[0] * s, lo[1] * s);
            p[1] = __floats2half2_rn(lo[2] * s, lo[3] * s);
        }
        if (rhi < M && tc * 4 < N) {
            float s = SCALE_NS ? g_ns[rhi] : 1.0f;
            __half2* p = reinterpret_cast<__half2*>(&outh[(long long)rhi * N + tc * 4]);
            p[0] = __floats2half2_rn(hi[0] * s, hi[1] * s);
            p[1] = __floats2half2_rn(hi[2] * s, hi[3] * s);
        }
    }
}

// ---------------------------------------------------------------------------
// Fused SpMM-gather (fp16 features, uint4 loads = 8 halves per lane, fp32
// accumulate) + nd + bias + [relu] + log_softmax. Warp per dst row.
// CH = F/8 lanes per edge (16B each), G = 32/CH edge groups in flight.
// All conversions by value (no address-of -> no spills).
// ---------------------------------------------------------------------------
template<int F, bool RELU, bool APPLY_NS>
__global__ void spmm_fused_kernel(const float* __restrict__ bias, int n,
                                  float* __restrict__ outp) {
    constexpr int CH = F / 8;       // 16B chunks per row (8 halves each)
    constexpr int G = 32 / CH;      // edge groups per warp (F=64: 4, F=40: 6)

    int row = blockIdx.x * (blockDim.x >> 5) + (threadIdx.x >> 5);
    if (row >= n) return;
    int lane = threadIdx.x & 31;
    int g = lane / CH;
    int sub = lane - g * CH;

    const __half* hA = reinterpret_cast<const __half*>(g_bufA);

    int start = g_rowptr[row];
    int end = g_rowptr[row + 1];

    float acc[8];
#pragma unroll
    for (int j = 0; j < 8; j++) acc[j] = 0.f;

    if (g < G) {
#pragma unroll 2
        for (int e = start + g; e < end; e += G) {
            int s = g_col[e];
            float w = APPLY_NS ? g_ns[s] : 1.0f;
            uint4 u = *reinterpret_cast<const uint4*>(hA + (long long)s * F + sub * 8);
            float2 f0 = h2f2(u.x);
            float2 f1 = h2f2(u.y);
            float2 f2 = h2f2(u.z);
            float2 f3 = h2f2(u.w);
            if (APPLY_NS) {
                acc[0] = fmaf(w, f0.x, acc[0]); acc[1] = fmaf(w, f0.y, acc[1]);
                acc[2] = fmaf(w, f1.x, acc[2]); acc[3] = fmaf(w, f1.y, acc[3]);
                acc[4] = fmaf(w, f2.x, acc[4]); acc[5] = fmaf(w, f2.y, acc[5]);
                acc[6] = fmaf(w, f3.x, acc[6]); acc[7] = fmaf(w, f3.y, acc[7]);
            } else {
                acc[0] += f0.x; acc[1] += f0.y; acc[2] += f1.x; acc[3] += f1.y;
                acc[4] += f2.x; acc[5] += f2.y; acc[6] += f3.x; acc[7] += f3.y;
            }
        }
    }

    // Combine edge groups into group 0 (snapshot reads; srcLane < 32 always).
    float tot[8];
#pragma unroll
    for (int j = 0; j < 8; j++) tot[j] = acc[j];
#pragma unroll
    for (int k = 1; k < G; k++) {
#pragma unroll
        for (int j = 0; j < 8; j++)
            tot[j] += __shfl_sync(0xffffffffu, acc[j], sub + k * CH);
    }

    float ndv = g_nd[row];
    float x[8];
    {
        const float4* bp = reinterpret_cast<const float4*>(bias + sub * 8);
        float4 b0 = bp[0], b1 = bp[1];
        x[0] = tot[0] * ndv + b0.x; x[1] = tot[1] * ndv + b0.y;
        x[2] = tot[2] * ndv + b0.z; x[3] = tot[3] * ndv + b0.w;
        x[4] = tot[4] * ndv + b1.x; x[5] = tot[5] * ndv + b1.y;
        x[6] = tot[6] * ndv + b1.z; x[7] = tot[7] * ndv + b1.w;
    }
    if (RELU) {
#pragma unroll
        for (int j = 0; j < 8; j++) x[j] = fmaxf(x[j], 0.f);
    }

    // Row reduction over the first 8 lanes (valid = lanes 0..CH-1; neutral pad).
    bool valid = (lane < CH);
    float m = -FLT_MAX;
    if (valid) {
#pragma unroll
        for (int j = 0; j < 8; j++) m = fmaxf(m, x[j]);
    }
#pragma unroll
    for (int o = 4; o > 0; o >>= 1) m = fmaxf(m, __shfl_xor_sync(0xffffffffu, m, o));
    float s = 0.f;
    if (valid) {
#pragma unroll
        for (int j = 0; j < 8; j++) s += expf(x[j] - m);
    }
#pragma unroll
    for (int o = 4; o > 0; o >>= 1) s += __shfl_xor_sync(0xffffffffu, s, o);
    float ls = m + logf(s);

    if (valid) {
        float* out = outp ? outp : g_bufB;
        float4 r0, r1;
        r0.x = x[0] - ls; r0.y = x[1] - ls; r0.z = x[2] - ls; r0.w = x[3] - ls;
        r1.x = x[4] - ls; r1.y = x[5] - ls; r1.z = x[6] - ls; r1.w = x[7] - ls;
        float4* op = reinterpret_cast<float4*>(out + (long long)row * F + sub * 8);
        op[0] = r0; op[1] = r1;
    }
}

// ---------------------------------------------------------------------------
// Launch. CSR build forked onto a side stream; GEMM0 overlaps it.
// ---------------------------------------------------------------------------
extern "C" void kernel_launch(void* const* d_in, const int* in_sizes, int n_in,
                              void* d_out, int out_size) {
    const float* feats = (const float*)d_in[0];
    const int*   src   = (const int*)d_in[1];
    const int*   dst   = (const int*)d_in[2];
    const float* W0    = (const float*)d_in[3];
    const float* b0    = (const float*)d_in[4];
    const float* W1    = (const float*)d_in[5];
    const float* b1    = (const float*)d_in[6];
    const float* W2    = (const float*)d_in[7];
    const float* b2    = (const float*)d_in[8];

    int N = in_sizes[0] / 128;   // 100000
    int E = in_sizes[1];         // 1600000
    float* outp = (float*)d_out;

    static cudaStream_t s1 = nullptr;
    static cudaEvent_t evFork = nullptr, evJoin = nullptr;
    if (s1 == nullptr) {
        cudaStreamCreateWithFlags(&s1, cudaStreamNonBlocking);
        cudaEventCreateWithFlags(&evFork, cudaEventDisableTiming);
        cudaEventCreateWithFlags(&evJoin, cudaEventDisableTiming);
    }

    int scan_blocks = (N + SCAN_TILE - 1) / SCAN_TILE;
    int spmm_blocks = (N + 7) / 8;
    int gemm_blocks = (N + 63) / 64;

    // ---- fork: CSR build + norms on side stream ----
    cudaEventRecord(evFork, 0);
    cudaStreamWaitEvent(s1, evFork, 0);
    zero_deg_kernel<<<(N + 255) / 256, 256, 0, s1>>>(N);
    deg_kernel<<<(E + 255) / 256, 256, 0, s1>>>(src, dst, E);
    scan_reduce_kernel<<<scan_blocks, 256, 0, s1>>>(N);
    scan_blksums_kernel<<<1, 128, 0, s1>>>(scan_blocks, N);
    scan_write_kernel<<<scan_blocks, 256, 0, s1>>>(N);
    fill_kernel<<<(E + 255) / 256, 256, 0, s1>>>(src, dst, E);
    cudaEventRecord(evJoin, s1);

    // ---- concurrently: layer-0 GEMM (no ns) ----
    gemm_ns_kernel<128, 64, false><<<gemm_blocks, 256>>>(feats, W0, N);

    // ---- join, then layer-0 gather applies ns per edge ----
    cudaStreamWaitEvent(0, evJoin, 0);
    spmm_fused_kernel<64, true, true><<<spmm_blocks, 256>>>(b0, N, nullptr);

    // ---- layer 1 ----
    gemm_ns_kernel<64, 64, true><<<gemm_blocks, 256>>>(nullptr, W1, N);
    spmm_fused_kernel<64, true, false><<<spmm_blocks, 256>>>(b1, N, nullptr);

    // ---- layer 2 ----
    gemm_ns_kernel<64, 40, true><<<gemm_blocks, 256>>>(nullptr, W2, N);
    spmm_fused_kernel<40, false, false><<<spmm_blocks, 256>>>(b2, N, outp);
}

// round 14
// speedup vs baseline: 1.0936x; 1.0936x over previous
#include <cuda_runtime.h>
#include <cuda_fp16.h>
#include <math.h>
#include <float.h>

#define MAX_NODES 100000
#define MAX_EDGES 1600000
#define SCAN_TILE 1024
#define MAX_SCAN_BLOCKS 128

// Scratch — referenced directly from device code.
// g_bufA viewed as __half[...] (gather operand); g_bufB stays fp32.
__device__ __align__(16) float g_bufA[MAX_NODES * 64];
__device__ __align__(16) float g_bufB[MAX_NODES * 64];
__device__ __align__(16) int g_deg_out[MAX_NODES];
__device__ __align__(16) int g_deg_in[MAX_NODES];
__device__ int   g_rowptr[MAX_NODES + 1];
__device__ int   g_cursor[MAX_NODES];
__device__ int   g_col[MAX_EDGES];
__device__ __align__(16) float g_ns[MAX_NODES];
__device__ __align__(16) float g_nd[MAX_NODES];
__device__ int   g_blksum[MAX_SCAN_BLOCKS];
__device__ int   g_blkoff[MAX_SCAN_BLOCKS];

// Register-only fp16x2 -> float2 conversion (no address-of -> no local spill).
__device__ __forceinline__ float2 h2f2(unsigned v) {
    float2 f;
    asm("{\n\t.reg .b16 lo, hi;\n\t"
        "mov.b32 {lo, hi}, %2;\n\t"
        "cvt.f32.f16 %0, lo;\n\t"
        "cvt.f32.f16 %1, hi;\n\t}"
        : "=f"(f.x), "=f"(f.y) : "r"(v));
    return f;
}

// ---------------------------------------------------------------------------
// CSR build, edge passes vectorized 4 edges/thread (E % 4 == 0 here; tail-safe).
// ---------------------------------------------------------------------------
__global__ void zero_deg_kernel(int n) {
    int i = (blockIdx.x * blockDim.x + threadIdx.x) * 4;
    if (i < n) {   // n % 4 == 0
        *reinterpret_cast<int4*>(&g_deg_out[i]) = make_int4(0, 0, 0, 0);
        *reinterpret_cast<int4*>(&g_deg_in[i]) = make_int4(0, 0, 0, 0);
    }
}

__global__ void deg_kernel(const int* __restrict__ src,
                           const int* __restrict__ dst, int E) {
    int i = (blockIdx.x * blockDim.x + threadIdx.x) * 4;
    if (i + 3 < E) {
        int4 s = *reinterpret_cast<const int4*>(&src[i]);
        int4 d = *reinterpret_cast<const int4*>(&dst[i]);
        atomicAdd(&g_deg_out[s.x], 1); atomicAdd(&g_deg_out[s.y], 1);
        atomicAdd(&g_deg_out[s.z], 1); atomicAdd(&g_deg_out[s.w], 1);
        atomicAdd(&g_deg_in[d.x], 1); atomicAdd(&g_deg_in[d.y], 1);
        atomicAdd(&g_deg_in[d.z], 1); atomicAdd(&g_deg_in[d.w], 1);
    } else {
        for (int e = i; e < E; e++) {
            atomicAdd(&g_deg_out[src[e]], 1);
            atomicAdd(&g_deg_in[dst[e]], 1);
        }
    }
}

// ---------------------------------------------------------------------------
// Grid-wide exclusive scan of g_deg_in -> g_rowptr/g_cursor (+ fused norms).
// ---------------------------------------------------------------------------
__device__ __forceinline__ int warp_incl_scan(int v, int lane) {
#pragma unroll
    for (int o = 1; o < 32; o <<= 1) {
        int t = __shfl_up_sync(0xffffffffu, v, o);
        if (lane >= o) v += t;
    }
    return v;
}

__global__ void scan_reduce_kernel(int n) {
    __shared__ int wsum[8];
    int tid = threadIdx.x, lane = tid & 31, wid = tid >> 5;
    int base = blockIdx.x * SCAN_TILE + tid * 4;
    int s = 0;
    if (base < n) {
        int4 v = *reinterpret_cast<const int4*>(&g_deg_in[base]);
        s = v.x + v.y + v.z + v.w;
    }
#pragma unroll
    for (int o = 16; o > 0; o >>= 1) s += __shfl_xor_sync(0xffffffffu, s, o);
    if (lane == 0) wsum[wid] = s;
    __syncthreads();
    if (tid == 0) {
        int t = 0;
#pragma unroll
        for (int w = 0; w < 8; w++) t += wsum[w];
        g_blksum[blockIdx.x] = t;
    }
}

__global__ void scan_blksums_kernel(int nb, int n) {
    __shared__ int woff[4];
    int tid = threadIdx.x, lane = tid & 31, wid = tid >> 5;
    int v = (tid < nb) ? g_blksum[tid] : 0;
    int incl = warp_incl_scan(v, lane);
    if (lane == 31) woff[wid] = incl;
    __syncthreads();
    if (tid == 0) {
        int acc = 0;
#pragma unroll
        for (int w = 0; w < 4; w++) { int t = woff[w]; woff[w] = acc; acc += t; }
    }
    __syncthreads();
    int excl = incl - v + woff[wid];
    if (tid < nb) g_blkoff[tid] = excl;
    if (tid == nb - 1) g_rowptr[n] = excl + v;
}

__device__ __forceinline__ float deg_norm(int d) {
    return (d > 0) ? rsqrtf((float)d) : 0.0f;
}

__global__ void scan_write_kernel(int n) {
    __shared__ int woff[8];
    int tid = threadIdx.x, lane = tid & 31, wid = tid >> 5;
    int base = blockIdx.x * SCAN_TILE + tid * 4;
    int4 v = make_int4(0, 0, 0, 0);
    if (base < n) v = *reinterpret_cast<const int4*>(&g_deg_in[base]);
    int s = v.x + v.y + v.z + v.w;
    int incl = warp_incl_scan(s, lane);
    if (lane == 31) woff[wid] = incl;
    __syncthreads();
    if (tid == 0) {
        int acc = 0;
#pragma unroll
        for (int w = 0; w < 8; w++) { int t = woff[w]; woff[w] = acc; acc += t; }
    }
    __syncthreads();
    if (base < n) {
        int excl = incl - s + woff[wid] + g_blkoff[blockIdx.x];
        int p0 = excl, p1 = p0 + v.x, p2 = p1 + v.y, p3 = p2 + v.z;
        *reinterpret_cast<int4*>(&g_rowptr[base]) = make_int4(p0, p1, p2, p3);
        *reinterpret_cast<int4*>(&g_cursor[base]) = make_int4(p0, p1, p2, p3);
        int4 o = *reinterpret_cast<const int4*>(&g_deg_out[base]);
        *reinterpret_cast<float4*>(&g_ns[base]) =
            make_float4(deg_norm(o.x), deg_norm(o.y), deg_norm(o.z), deg_norm(o.w));
        *reinterpret_cast<float4*>(&g_nd[base]) =
            make_float4(deg_norm(v.x), deg_norm(v.y), deg_norm(v.z), deg_norm(v.w));
    }
}

__global__ void fill_kernel(const int* __restrict__ src,
                            const int* __restrict__ dst, int E) {
    int i = (blockIdx.x * blockDim.x + threadIdx.x) * 4;
    if (i + 3 < E) {
        int4 s = *reinterpret_cast<const int4*>(&src[i]);
        int4 d = *reinterpret_cast<const int4*>(&dst[i]);
        g_col[atomicAdd(&g_cursor[d.x], 1)] = s.x;
        g_col[atomicAdd(&g_cursor[d.y], 1)] = s.y;
        g_col[atomicAdd(&g_cursor[d.z], 1)] = s.z;
        g_col[atomicAdd(&g_cursor[d.w], 1)] = s.w;
    } else {
        for (int e = i; e < E; e++)
            g_col[atomicAdd(&g_cursor[dst[e]], 1)] = src[e];
    }
}

// ---------------------------------------------------------------------------
// GEMM (packed f32x2): halfA[M,N] = half((X[M,K] @ W[K,N]) [* g_ns[row]])
// ---------------------------------------------------------------------------
#define AS_S 68

template<int K, int N, bool SCALE_NS>
__global__ void gemm_ns_kernel(const float* __restrict__ Xext,
                               const float* __restrict__ W, int M) {
    __shared__ __align__(16) float Ws[K * 64];
    __shared__ __align__(16) float As[32 * AS_S];

    const float* X = Xext ? Xext : g_bufB;
    __half* outh = reinterpret_cast<__half*>(g_bufA);
    const int tid = threadIdx.x;
    const int tr = tid >> 4;
    const int tc = tid & 15;
    const int row0 = blockIdx.x * 64;

    for (int t = tid; t < K * 64; t += 256) {
        int k = t >> 6, c = t & 63;
        Ws[t] = (c < N) ? W[k * N + c] : 0.0f;
    }

    unsigned long long acc[2][4];
#pragma unroll
    for (int rp = 0; rp < 2; rp++)
#pragma unroll
        for (int c = 0; c < 4; c++) acc[rp][c] = 0ull;

    for (int k0 = 0; k0 < K; k0 += 32) {
        __syncthreads();
#pragma unroll
        for (int it = 0; it < 2; it++) {
            int idx = tid + it * 256;
            int row = idx >> 3;
            int kc = idx & 7;
            float4 v = make_float4(0.f, 0.f, 0.f, 0.f);
            if (row0 + row < M)
                v = *reinterpret_cast<const float4*>(&X[(long long)(row0 + row) * K + k0 + kc * 4]);
            As[(kc * 4 + 0) * AS_S + row] = v.x;
            As[(kc * 4 + 1) * AS_S + row] = v.y;
            As[(kc * 4 + 2) * AS_S + row] = v.z;
            As[(kc * 4 + 3) * AS_S + row] = v.w;
        }
        __syncthreads();

#pragma unroll
        for (int kk = 0; kk < 32; kk++) {
            float4 a4 = *reinterpret_cast<const float4*>(&As[kk * AS_S + tr * 4]);
            float4 b4 = *reinterpret_cast<const float4*>(&Ws[(k0 + kk) * 64 + tc * 4]);
            unsigned long long a01, a23, bb0, bb1, bb2, bb3;
            asm("mov.b64 %0, {%1, %2};" : "=l"(a01) : "f"(a4.x), "f"(a4.y));
            asm("mov.b64 %0, {%1, %2};" : "=l"(a23) : "f"(a4.z), "f"(a4.w));
            asm("mov.b64 %0, {%1, %1};" : "=l"(bb0) : "f"(b4.x));
            asm("mov.b64 %0, {%1, %1};" : "=l"(bb1) : "f"(b4.y));
            asm("mov.b64 %0, {%1, %1};" : "=l"(bb2) : "f"(b4.z));
            asm("mov.b64 %0, {%1, %1};" : "=l"(bb3) : "f"(b4.w));
            asm("fma.rn.f32x2 %0, %1, %2, %0;" : "+l"(acc[0][0]) : "l"(a01), "l"(bb0));
            asm("fma.rn.f32x2 %0, %1, %2, %0;" : "+l"(acc[0][1]) : "l"(a01), "l"(bb1));
            asm("fma.rn.f32x2 %0, %1, %2, %0;" : "+l"(acc[0][2]) : "l"(a01), "l"(bb2));
            asm("fma.rn.f32x2 %0, %1, %2, %0;" : "+l"(acc[0][3]) : "l"(a01), "l"(bb3));
            asm("fma.rn.f32x2 %0, %1, %2, %0;" : "+l"(acc[1][0]) : "l"(a23), "l"(bb0));
            asm("fma.rn.f32x2 %0, %1, %2, %0;" : "+l"(acc[1][1]) : "l"(a23), "l"(bb1));
            asm("fma.rn.f32x2 %0, %1, %2, %0;" : "+l"(acc[1][2]) : "l"(a23), "l"(bb2));
            asm("fma.rn.f32x2 %0, %1, %2, %0;" : "+l"(acc[1][3]) : "l"(a23), "l"(bb3));
        }
    }

#pragma unroll
    for (int rp = 0; rp < 2; rp++) {
        float lo[4], hi[4];
#pragma unroll
        for (int c = 0; c < 4; c++)
            asm("mov.b64 {%0, %1}, %2;" : "=f"(lo[c]), "=f"(hi[c]) : "l"(acc[rp][c]));
        int rlo = row0 + tr * 4 + rp * 2;
        int rhi = rlo + 1;
        if (rlo < M && tc * 4 < N) {
            float s = SCALE_NS ? g_ns[rlo] : 1.0f;
            __half2* p = reinterpret_cast<__half2*>(&outh[(long long)rlo * N + tc * 4]);
            p[0] = __floats2half2_rn(lo[0] * s, lo[1] * s);
            p[1] = __floats2half2_rn(lo[2] * s, lo[3] * s);
        }
        if (rhi < M && tc * 4 < N) {
            float s = SCALE_NS ? g_ns[rhi] : 1.0f;
            __half2* p = reinterpret_cast<__half2*>(&outh[(long long)rhi * N + tc * 4]);
            p[0] = __floats2half2_rn(hi[0] * s, hi[1] * s);
            p[1] = __floats2half2_rn(hi[2] * s, hi[3] * s);
        }
    }
}

// ---------------------------------------------------------------------------
// Fused SpMM-gather (fp16 features, uint2 loads, fp32 accumulate) + nd + bias
// + [relu] + log_softmax. Warp per dst row. R12 lane structure (best so far):
// CH = F/4 lanes per edge, 4 values per lane, G = 32/CH edge groups.
// ---------------------------------------------------------------------------
template<int F, bool RELU, bool APPLY_NS>
__global__ void __launch_bounds__(256) spmm_fused_kernel(
        const float* __restrict__ bias, int n, float* __restrict__ outp) {
    constexpr int CH = F / 4;
    constexpr int G = 32 / CH;

    int row = blockIdx.x * (blockDim.x >> 5) + (threadIdx.x >> 5);
    if (row >= n) return;
    int lane = threadIdx.x & 31;
    int g = lane / CH;
    int sub = lane - g * CH;

    const __half* hA = reinterpret_cast<const __half*>(g_bufA);

    int start = g_rowptr[row];
    int end = g_rowptr[row + 1];

    float4 acc = make_float4(0.f, 0.f, 0.f, 0.f);
    if (g < G) {
#pragma unroll 4
        for (int e = start + g; e < end; e += G) {
            int s = g_col[e];
            float w = APPLY_NS ? g_ns[s] : 1.0f;
            uint2 u = *reinterpret_cast<const uint2*>(hA + (long long)s * F + sub * 4);
            float2 f0 = h2f2(u.x);
            float2 f1 = h2f2(u.y);
            if (APPLY_NS) {
                acc.x = fmaf(w, f0.x, acc.x);
                acc.y = fmaf(w, f0.y, acc.y);
                acc.z = fmaf(w, f1.x, acc.z);
                acc.w = fmaf(w, f1.y, acc.w);
            } else {
                acc.x += f0.x; acc.y += f0.y; acc.z += f1.x; acc.w += f1.y;
            }
        }
    }

    float4 tot = acc;
#pragma unroll
    for (int k = 1; k < G; k++) {
        tot.x += __shfl_sync(0xffffffffu, acc.x, sub + k * CH);
        tot.y += __shfl_sync(0xffffffffu, acc.y, sub + k * CH);
        tot.z += __shfl_sync(0xffffffffu, acc.z, sub + k * CH);
        tot.w += __shfl_sync(0xffffffffu, acc.w, sub + k * CH);
    }

    float ndv = g_nd[row];
    float4 bv = *reinterpret_cast<const float4*>(bias + sub * 4);
    float4 x;
    x.x = tot.x * ndv + bv.x;
    x.y = tot.y * ndv + bv.y;
    x.z = tot.z * ndv + bv.z;
    x.w = tot.w * ndv + bv.w;
    if (RELU) {
        x.x = fmaxf(x.x, 0.f); x.y = fmaxf(x.y, 0.f);
        x.z = fmaxf(x.z, 0.f); x.w = fmaxf(x.w, 0.f);
    }

    bool valid = (lane < CH);
    float m = valid ? fmaxf(fmaxf(x.x, x.y), fmaxf(x.z, x.w)) : -FLT_MAX;
#pragma unroll
    for (int o = 8; o > 0; o >>= 1) m = fmaxf(m, __shfl_xor_sync(0xffffffffu, m, o));
    float s = valid ? (expf(x.x - m) + expf(x.y - m) + expf(x.z - m) + expf(x.w - m)) : 0.f;
#pragma unroll
    for (int o = 8; o > 0; o >>= 1) s += __shfl_xor_sync(0xffffffffu, s, o);
    float ls = m + logf(s);

    if (valid) {
        float* out = outp ? outp : g_bufB;
        float4 r;
        r.x = x.x - ls; r.y = x.y - ls; r.z = x.z - ls; r.w = x.w - ls;
        *reinterpret_cast<float4*>(out + (long long)row * F + sub * 4) = r;
    }
}

// ---------------------------------------------------------------------------
// Launch. CSR build forked onto a side stream; GEMM0 overlaps it.
// ---------------------------------------------------------------------------
extern "C" void kernel_launch(void* const* d_in, const int* in_sizes, int n_in,
                              void* d_out, int out_size) {
    const float* feats = (const float*)d_in[0];
    const int*   src   = (const int*)d_in[1];
    const int*   dst   = (const int*)d_in[2];
    const float* W0    = (const float*)d_in[3];
    const float* b0    = (const float*)d_in[4];
    const float* W1    = (const float*)d_in[5];
    const float* b1    = (const float*)d_in[6];
    const float* W2    = (const float*)d_in[7];
    const float* b2    = (const float*)d_in[8];

    int N = in_sizes[0] / 128;   // 100000
    int E = in_sizes[1];         // 1600000
    float* outp = (float*)d_out;

    static cudaStream_t s1 = nullptr;
    static cudaEvent_t evFork = nullptr, evJoin = nullptr;
    if (s1 == nullptr) {
        cudaStreamCreateWithFlags(&s1, cudaStreamNonBlocking);
        cudaEventCreateWithFlags(&evFork, cudaEventDisableTiming);
        cudaEventCreateWithFlags(&evJoin, cudaEventDisableTiming);
    }

    int scan_blocks = (N + SCAN_TILE - 1) / SCAN_TILE;
    int spmm_blocks = (N + 7) / 8;
    int gemm_blocks = (N + 63) / 64;
    int edge4_blocks = ((E + 3) / 4 + 255) / 256;

    // ---- fork: CSR build + norms on side stream ----
    cudaEventRecord(evFork, 0);
    cudaStreamWaitEvent(s1, evFork, 0);
    zero_deg_kernel<<<(N / 4 + 255) / 256, 256, 0, s1>>>(N);
    deg_kernel<<<edge4_blocks, 256, 0, s1>>>(src, dst, E);
    scan_reduce_kernel<<<scan_blocks, 256, 0, s1>>>(N);
    scan_blksums_kernel<<<1, 128, 0, s1>>>(scan_blocks, N);
    scan_write_kernel<<<scan_blocks, 256, 0, s1>>>(N);
    fill_kernel<<<edge4_blocks, 256, 0, s1>>>(src, dst, E);
    cudaEventRecord(evJoin, s1);

    // ---- concurrently: layer-0 GEMM (no ns) ----
    gemm_ns_kernel<128, 64, false><<<gemm_blocks, 256>>>(feats, W0, N);

    // ---- join, then layer-0 gather applies ns per edge ----
    cudaStreamWaitEvent(0, evJoin, 0);
    spmm_fused_kernel<64, true, true><<<spmm_blocks, 256>>>(b0, N, nullptr);

    // ---- layer 1 ----
    gemm_ns_kernel<64, 64, true><<<gemm_blocks, 256>>>(nullptr, W1, N);
    spmm_fused_kernel<64, true, false><<<spmm_blocks, 256>>>(b1, N, nullptr);

    // ---- layer 2 ----
    gemm_ns_kernel<64, 40, true><<<gemm_blocks, 256>>>(nullptr, W2, N);
    spmm_fused_kernel<40, false, false><<<spmm_blocks, 256>>>(b2, N, outp);
}

// round 15
// speedup vs baseline: 1.3053x; 1.1936x over previous
#include <cuda_runtime.h>
#include <cuda_fp16.h>
#include <math.h>
#include <float.h>

#define MAX_NODES 100000
#define MAX_EDGES 1600000
#define SCAN_TILE 1024
#define MAX_SCAN_BLOCKS 128

// Scratch — referenced directly from device code.
// g_bufA viewed as __half[...] (gather operand); g_bufB stays fp32.
__device__ __align__(16) float g_bufA[MAX_NODES * 64];
__device__ __align__(16) float g_bufB[MAX_NODES * 64];
__device__ __align__(16) int g_deg_out[MAX_NODES];
__device__ __align__(16) int g_deg_in[MAX_NODES];
__device__ int   g_rowptr[MAX_NODES + 1];
__device__ int   g_cursor[MAX_NODES];
__device__ int   g_col[MAX_EDGES];
__device__ __align__(16) float g_ns[MAX_NODES];
__device__ __align__(16) float g_nd[MAX_NODES];
__device__ int   g_blksum[MAX_SCAN_BLOCKS];
__device__ int   g_blkoff[MAX_SCAN_BLOCKS];

// Register-only fp16x2 -> float2 conversion (no address-of -> no local spill).
__device__ __forceinline__ float2 h2f2(unsigned v) {
    float2 f;
    asm("{\n\t.reg .b16 lo, hi;\n\t"
        "mov.b32 {lo, hi}, %2;\n\t"
        "cvt.f32.f16 %0, lo;\n\t"
        "cvt.f32.f16 %1, hi;\n\t}"
        : "=f"(f.x), "=f"(f.y) : "r"(v));
    return f;
}

__device__ __forceinline__ unsigned smem_u32(const void* p) {
    unsigned a;
    asm("{ .reg .u64 t; cvta.to.shared.u64 t, %1; cvt.u32.u64 %0, t; }"
        : "=r"(a) : "l"(p));
    return a;
}

__device__ __forceinline__ void ldsm_x4(unsigned* a, unsigned addr) {
    asm volatile("ldmatrix.sync.aligned.m8n8.x4.shared.b16 {%0,%1,%2,%3}, [%4];"
        : "=r"(a[0]), "=r"(a[1]), "=r"(a[2]), "=r"(a[3]) : "r"(addr));
}
__device__ __forceinline__ void ldsm_x2t(unsigned* b, unsigned addr) {
    asm volatile("ldmatrix.sync.aligned.m8n8.x2.trans.shared.b16 {%0,%1}, [%2];"
        : "=r"(b[0]), "=r"(b[1]) : "r"(addr));
}
__device__ __forceinline__ void mma_f16(float* c, const unsigned* a, const unsigned* b) {
    asm volatile("mma.sync.aligned.m16n8k16.row.col.f32.f16.f16.f32 "
        "{%0,%1,%2,%3}, {%4,%5,%6,%7}, {%8,%9}, {%0,%1,%2,%3};"
        : "+f"(c[0]), "+f"(c[1]), "+f"(c[2]), "+f"(c[3])
        : "r"(a[0]), "r"(a[1]), "r"(a[2]), "r"(a[3]), "r"(b[0]), "r"(b[1]));
}

// ---------------------------------------------------------------------------
// CSR build (scalar edge passes — R12 config, best measured).
// ---------------------------------------------------------------------------
__global__ void zero_deg_kernel(int n) {
    int i = blockIdx.x * blockDim.x + threadIdx.x;
    if (i < n) { g_deg_out[i] = 0; g_deg_in[i] = 0; }
}

__global__ void deg_kernel(const int* __restrict__ src,
                           const int* __restrict__ dst, int E) {
    int i = blockIdx.x * blockDim.x + threadIdx.x;
    if (i < E) {
        atomicAdd(&g_deg_out[src[i]], 1);
        atomicAdd(&g_deg_in[dst[i]], 1);
    }
}

__device__ __forceinline__ int warp_incl_scan(int v, int lane) {
#pragma unroll
    for (int o = 1; o < 32; o <<= 1) {
        int t = __shfl_up_sync(0xffffffffu, v, o);
        if (lane >= o) v += t;
    }
    return v;
}

__global__ void scan_reduce_kernel(int n) {
    __shared__ int wsum[8];
    int tid = threadIdx.x, lane = tid & 31, wid = tid >> 5;
    int base = blockIdx.x * SCAN_TILE + tid * 4;
    int s = 0;
    if (base < n) {
        int4 v = *reinterpret_cast<const int4*>(&g_deg_in[base]);
        s = v.x + v.y + v.z + v.w;
    }
#pragma unroll
    for (int o = 16; o > 0; o >>= 1) s += __shfl_xor_sync(0xffffffffu, s, o);
    if (lane == 0) wsum[wid] = s;
    __syncthreads();
    if (tid == 0) {
        int t = 0;
#pragma unroll
        for (int w = 0; w < 8; w++) t += wsum[w];
        g_blksum[blockIdx.x] = t;
    }
}

__global__ void scan_blksums_kernel(int nb, int n) {
    __shared__ int woff[4];
    int tid = threadIdx.x, lane = tid & 31, wid = tid >> 5;
    int v = (tid < nb) ? g_blksum[tid] : 0;
    int incl = warp_incl_scan(v, lane);
    if (lane == 31) woff[wid] = incl;
    __syncthreads();
    if (tid == 0) {
        int acc = 0;
#pragma unroll
        for (int w = 0; w < 4; w++) { int t = woff[w]; woff[w] = acc; acc += t; }
    }
    __syncthreads();
    int excl = incl - v + woff[wid];
    if (tid < nb) g_blkoff[tid] = excl;
    if (tid == nb - 1) g_rowptr[n] = excl + v;
}

__device__ __forceinline__ float deg_norm(int d) {
    return (d > 0) ? rsqrtf((float)d) : 0.0f;
}

__global__ void scan_write_kernel(int n) {
    __shared__ int woff[8];
    int tid = threadIdx.x, lane = tid & 31, wid = tid >> 5;
    int base = blockIdx.x * SCAN_TILE + tid * 4;
    int4 v = make_int4(0, 0, 0, 0);
    if (base < n) v = *reinterpret_cast<const int4*>(&g_deg_in[base]);
    int s = v.x + v.y + v.z + v.w;
    int incl = warp_incl_scan(s, lane);
    if (lane == 31) woff[wid] = incl;
    __syncthreads();
    if (tid == 0) {
        int acc = 0;
#pragma unroll
        for (int w = 0; w < 8; w++) { int t = woff[w]; woff[w] = acc; acc += t; }
    }
    __syncthreads();
    if (base < n) {
        int excl = incl - s + woff[wid] + g_blkoff[blockIdx.x];
        int p0 = excl, p1 = p0 + v.x, p2 = p1 + v.y, p3 = p2 + v.z;
        *reinterpret_cast<int4*>(&g_rowptr[base]) = make_int4(p0, p1, p2, p3);
        *reinterpret_cast<int4*>(&g_cursor[base]) = make_int4(p0, p1, p2, p3);
        int4 o = *reinterpret_cast<const int4*>(&g_deg_out[base]);
        *reinterpret_cast<float4*>(&g_ns[base]) =
            make_float4(deg_norm(o.x), deg_norm(o.y), deg_norm(o.z), deg_norm(o.w));
        *reinterpret_cast<float4*>(&g_nd[base]) =
            make_float4(deg_norm(v.x), deg_norm(v.y), deg_norm(v.z), deg_norm(v.w));
    }
}

__global__ void fill_kernel(const int* __restrict__ src,
                            const int* __restrict__ dst, int E) {
    int e = blockIdx.x * blockDim.x + threadIdx.x;
    if (e < E) {
        int d = dst[e];
        int pos = atomicAdd(&g_cursor[d], 1);
        g_col[pos] = src[e];
    }
}

// ---------------------------------------------------------------------------
// Tensor-core GEMM: halfA[M,N] = half((X[M,K] @ W[K,N]) [* g_ns[row]])
// mma.sync m16n8k16 fp16->fp32. Block = 8 warps, tile M=128 x N=64.
// A staged fp16 in smem in 64-col chunks; B staged fp16 fully.
// Strides 72 halves (36 words, %32=4) -> ldmatrix conflict-free.
// ---------------------------------------------------------------------------
template<int K, int N, bool SCALE_NS>
__global__ void __launch_bounds__(256) gemm_mma_kernel(
        const float* __restrict__ Xext, const float* __restrict__ W, int M) {
    __shared__ __half As[128 * 72];     // one 64-col K chunk
    __shared__ __half Bs[K * 72];       // full K x N (padded to 72)

    const float* X = Xext ? Xext : g_bufB;
    __half* outh = reinterpret_cast<__half*>(g_bufA);
    const int tid = threadIdx.x;
    const int lane = tid & 31;
    const int w = tid >> 5;
    const int wm = w & 3;               // m-tile: rows wm*32..+31
    const int wn = w >> 2;              // n-tile: cols wn*32..+31
    const int row0 = blockIdx.x * 128;

    // Stage B (fp32 -> fp16), zero-pad cols N..71.
    for (int t = tid; t < K * 72; t += 256) {
        int k = t / 72, n = t - k * 72;
        Bs[t] = (n < N) ? __float2half(W[k * N + n]) : __float2half(0.0f);
    }

    const unsigned as_base = smem_u32(As);
    const unsigned bs_base = smem_u32(Bs);

    float c_[2][4][4];
#pragma unroll
    for (int mt = 0; mt < 2; mt++)
#pragma unroll
        for (int nt = 0; nt < 4; nt++)
#pragma unroll
            for (int j = 0; j < 4; j++) c_[mt][nt][j] = 0.0f;

    constexpr int NCHUNK = K / 64;
    for (int kc = 0; kc < NCHUNK; kc++) {
        __syncthreads();   // protect As reuse
        // Stage A chunk: 128 rows x 64 cols, fp32 -> fp16.
        for (int t = tid; t < 128 * 16; t += 256) {
            int r = t >> 4, c = t & 15;
            int grow = row0 + r;
            __half2 h0 = __floats2half2_rn(0.f, 0.f), h1 = h0;
            if (grow < M) {
                float4 v = *reinterpret_cast<const float4*>(
                    &X[(size_t)grow * K + kc * 64 + c * 4]);
                h0 = __floats2half2_rn(v.x, v.y);
                h1 = __floats2half2_rn(v.z, v.w);
            }
            *reinterpret_cast<__half2*>(&As[r * 72 + c * 4]) = h0;
            *reinterpret_cast<__half2*>(&As[r * 72 + c * 4 + 2]) = h1;
        }
        __syncthreads();

#pragma unroll
        for (int ks = 0; ks < 4; ks++) {
            int kglob = kc * 64 + ks * 16;
            unsigned a[2][4], b[4][2];
#pragma unroll
            for (int mt = 0; mt < 2; mt++) {
                unsigned addr = as_base +
                    (((wm * 32 + mt * 16 + (lane & 15)) * 72 + ks * 16 + (lane >> 4) * 8) * 2);
                ldsm_x4(a[mt], addr);
            }
#pragma unroll
            for (int nt = 0; nt < 4; nt++) {
                unsigned addr = bs_base +
                    (((kglob + (lane & 15)) * 72 + wn * 32 + nt * 8) * 2);
                ldsm_x2t(b[nt], addr);
            }
#pragma unroll
            for (int mt = 0; mt < 2; mt++)
#pragma unroll
                for (int nt = 0; nt < 4; nt++)
                    mma_f16(c_[mt][nt], a[mt], b[nt]);
        }
    }

    // Epilogue: scale by ns, convert to fp16, store.
#pragma unroll
    for (int mt = 0; mt < 2; mt++) {
#pragma unroll
        for (int nt = 0; nt < 4; nt++) {
            int r = wm * 32 + mt * 16 + (lane >> 2);
            int col = wn * 32 + nt * 8 + (lane & 3) * 2;
            if (col < N) {
                int g0 = row0 + r, g1 = g0 + 8;
                if (g0 < M) {
                    float s = SCALE_NS ? g_ns[g0] : 1.0f;
                    *reinterpret_cast<__half2*>(&outh[(size_t)g0 * N + col]) =
                        __floats2half2_rn(c_[mt][nt][0] * s, c_[mt][nt][1] * s);
                }
                if (g1 < M) {
                    float s = SCALE_NS ? g_ns[g1] : 1.0f;
                    *reinterpret_cast<__half2*>(&outh[(size_t)g1 * N + col]) =
                        __floats2half2_rn(c_[mt][nt][2] * s, c_[mt][nt][3] * s);
                }
            }
        }
    }
}

// ---------------------------------------------------------------------------
// Fused SpMM-gather (fp16 features, uint2 loads, fp32 accumulate) + nd + bias
// + [relu] + log_softmax. Warp per dst row. R12 lane structure (best measured).
// ---------------------------------------------------------------------------
template<int F, bool RELU, bool APPLY_NS>
__global__ void __launch_bounds__(256) spmm_fused_kernel(
        const float* __restrict__ bias, int n, float* __restrict__ outp) {
    constexpr int CH = F / 4;
    constexpr int G = 32 / CH;

    int row = blockIdx.x * (blockDim.x >> 5) + (threadIdx.x >> 5);
    if (row >= n) return;
    int lane = threadIdx.x & 31;
    int g = lane / CH;
    int sub = lane - g * CH;

    const __half* hA = reinterpret_cast<const __half*>(g_bufA);

    int start = g_rowptr[row];
    int end = g_rowptr[row + 1];

    float4 acc = make_float4(0.f, 0.f, 0.f, 0.f);
    if (g < G) {
#pragma unroll 4
        for (int e = start + g; e < end; e += G) {
            int s = g_col[e];
            float w = APPLY_NS ? g_ns[s] : 1.0f;
            uint2 u = *reinterpret_cast<const uint2*>(hA + (long long)s * F + sub * 4);
            float2 f0 = h2f2(u.x);
            float2 f1 = h2f2(u.y);
            if (APPLY_NS) {
                acc.x = fmaf(w, f0.x, acc.x);
                acc.y = fmaf(w, f0.y, acc.y);
                acc.z = fmaf(w, f1.x, acc.z);
                acc.w = fmaf(w, f1.y, acc.w);
            } else {
                acc.x += f0.x; acc.y += f0.y; acc.z += f1.x; acc.w += f1.y;
            }
        }
    }

    float4 tot = acc;
#pragma unroll
    for (int k = 1; k < G; k++) {
        tot.x += __shfl_sync(0xffffffffu, acc.x, sub + k * CH);
        tot.y += __shfl_sync(0xffffffffu, acc.y, sub + k * CH);
        tot.z += __shfl_sync(0xffffffffu, acc.z, sub + k * CH);
        tot.w += __shfl_sync(0xffffffffu, acc.w, sub + k * CH);
    }

    float ndv = g_nd[row];
    float4 bv = *reinterpret_cast<const float4*>(bias + sub * 4);
    float4 x;
    x.x = tot.x * ndv + bv.x;
    x.y = tot.y * ndv + bv.y;
    x.z = tot.z * ndv + bv.z;
    x.w = tot.w * ndv + bv.w;
    if (RELU) {
        x.x = fmaxf(x.x, 0.f); x.y = fmaxf(x.y, 0.f);
        x.z = fmaxf(x.z, 0.f); x.w = fmaxf(x.w, 0.f);
    }

    bool valid = (lane < CH);
    float m = valid ? fmaxf(fmaxf(x.x, x.y), fmaxf(x.z, x.w)) : -FLT_MAX;
#pragma unroll
    for (int o = 8; o > 0; o >>= 1) m = fmaxf(m, __shfl_xor_sync(0xffffffffu, m, o));
    float s = valid ? (expf(x.x - m) + expf(x.y - m) + expf(x.z - m) + expf(x.w - m)) : 0.f;
#pragma unroll
    for (int o = 8; o > 0; o >>= 1) s += __shfl_xor_sync(0xffffffffu, s, o);
    float ls = m + logf(s);

    if (valid) {
        float* out = outp ? outp : g_bufB;
        float4 r;
        r.x = x.x - ls; r.y = x.y - ls; r.z = x.z - ls; r.w = x.w - ls;
        *reinterpret_cast<float4*>(out + (long long)row * F + sub * 4) = r;
    }
}

// ---------------------------------------------------------------------------
// Launch. CSR build forked onto a side stream; GEMM0 overlaps it.
// ---------------------------------------------------------------------------
extern "C" void kernel_launch(void* const* d_in, const int* in_sizes, int n_in,
                              void* d_out, int out_size) {
    const float* feats = (const float*)d_in[0];
    const int*   src   = (const int*)d_in[1];
    const int*   dst   = (const int*)d_in[2];
    const float* W0    = (const float*)d_in[3];
    const float* b0    = (const float*)d_in[4];
    const float* W1    = (const float*)d_in[5];
    const float* b1    = (const float*)d_in[6];
    const float* W2    = (const float*)d_in[7];
    const float* b2    = (const float*)d_in[8];

    int N = in_sizes[0] / 128;   // 100000
    int E = in_sizes[1];         // 1600000
    float* outp = (float*)d_out;

    static cudaStream_t s1 = nullptr;
    static cudaEvent_t evFork = nullptr, evJoin = nullptr;
    if (s1 == nullptr) {
        cudaStreamCreateWithFlags(&s1, cudaStreamNonBlocking);
        cudaEventCreateWithFlags(&evFork, cudaEventDisableTiming);
        cudaEventCreateWithFlags(&evJoin, cudaEventDisableTiming);
    }

    int scan_blocks = (N + SCAN_TILE - 1) / SCAN_TILE;
    int spmm_blocks = (N + 7) / 8;
    int gemm_blocks = (N + 127) / 128;

    // ---- fork: CSR build + norms on side stream ----
    cudaEventRecord(evFork, 0);
    cudaStreamWaitEvent(s1, evFork, 0);
    zero_deg_kernel<<<(N + 255) / 256, 256, 0, s1>>>(N);
    deg_kernel<<<(E + 255) / 256, 256, 0, s1>>>(src, dst, E);
    scan_reduce_kernel<<<scan_blocks, 256, 0, s1>>>(N);
    scan_blksums_kernel<<<1, 128, 0, s1>>>(scan_blocks, N);
    scan_write_kernel<<<scan_blocks, 256, 0, s1>>>(N);
    fill_kernel<<<(E + 255) / 256, 256, 0, s1>>>(src, dst, E);
    cudaEventRecord(evJoin, s1);

    // ---- concurrently: layer-0 GEMM (no ns) ----
    gemm_mma_kernel<128, 64, false><<<gemm_blocks, 256>>>(feats, W0, N);

    // ---- join, then layer-0 gather applies ns per edge ----
    cudaStreamWaitEvent(0, evJoin, 0);
    spmm_fused_kernel<64, true, true><<<spmm_blocks, 256>>>(b0, N, nullptr);

    // ---- layer 1 ----
    gemm_mma_kernel<64, 64, true><<<gemm_blocks, 256>>>(nullptr, W1, N);
    spmm_fused_kernel<64, true, false><<<spmm_blocks, 256>>>(b1, N, nullptr);

    // ---- layer 2 ----
    gemm_mma_kernel<64, 40, true><<<gemm_blocks, 256>>>(nullptr, W2, N);
    spmm_fused_kernel<40, false, false><<<spmm_blocks, 256>>>(b2, N, outp);
}